// round 13
// baseline (speedup 1.0000x reference)
#include <cuda_runtime.h>
#include <cuda_fp16.h>
#include <math.h>
#include <stdint.h>

// Problem constants
#define T_LEN 512
#define NBATCH 64
#define HID 512
#define G4 2048          // 4*HID
#define NVOCAB 10000

#define SCAN_BLOCKS 128
#define SCAN_THREADS 256
#define NPAD 36          // red buffer row stride (floats)

// -------- device scratch --------
__device__ __align__(16) __half g_E0h[(size_t)NVOCAB * G4];   // emb @ Wih0^T + b0 (fp16)
__device__ __align__(16) __half g_h0buf[2][NBATCH * HID];     // layer0 h ping-pong, frag layout
__device__ __align__(16) __half g_h1buf[2][NBATCH * HID];     // layer1 h ping-pong, frag layout
__device__ unsigned g_ctrs[2][64];                             // per-half barrier counters (256B apart)
__device__ int g_maxsl2[2];                                    // per-half max(sen_len)

// ---------------- helpers ----------------
__device__ __forceinline__ void mma_tf32(float* c, const unsigned* a, const unsigned* b) {
    asm("mma.sync.aligned.m16n8k8.row.col.f32.tf32.tf32.f32 "
        "{%0,%1,%2,%3}, {%4,%5,%6,%7}, {%8,%9}, {%0,%1,%2,%3};"
        : "+f"(c[0]), "+f"(c[1]), "+f"(c[2]), "+f"(c[3])
        : "r"(a[0]), "r"(a[1]), "r"(a[2]), "r"(a[3]), "r"(b[0]), "r"(b[1]));
}
__device__ __forceinline__ void mma_f16(float* c, const unsigned* a, const unsigned* b) {
    asm("mma.sync.aligned.m16n8k16.row.col.f32.f16.f16.f32 "
        "{%0,%1,%2,%3}, {%4,%5,%6,%7}, {%8,%9}, {%0,%1,%2,%3};"
        : "+f"(c[0]), "+f"(c[1]), "+f"(c[2]), "+f"(c[3])
        : "r"(a[0]), "r"(a[1]), "r"(a[2]), "r"(a[3]), "r"(b[0]), "r"(b[1]));
}
__device__ __forceinline__ unsigned ld_acq(const unsigned* p) {
    unsigned v; asm volatile("ld.acquire.gpu.global.u32 %0, [%1];" : "=r"(v) : "l"(p)); return v;
}
__device__ __forceinline__ uint4 ldcg4(const uint4* p) {
    uint4 v;
    asm volatile("ld.global.cg.v4.u32 {%0,%1,%2,%3}, [%4];"
                 : "=r"(v.x), "=r"(v.y), "=r"(v.z), "=r"(v.w) : "l"(p));
    return v;
}
__device__ __forceinline__ float tanh_ap(float x) {
    float y; asm("tanh.approx.f32 %0, %1;" : "=f"(y) : "f"(x)); return y;
}
// sigmoid via tanh: sig(x) = 0.5*tanh(x/2) + 0.5
__device__ __forceinline__ float sig_(float x) {
    return fmaf(0.5f, tanh_ap(0.5f * x), 0.5f);
}
// fp16 half-index for h value (batch b, unit k) in m16n8k16 A-fragment layout.
__device__ __forceinline__ int hidx16(int b, int k) {
    int kk = k >> 4, mt = b >> 4, r = b & 15, kl = k & 15;
    int lane = (r & 7) * 4 + ((kl & 7) >> 1);
    int w = ((kl >> 3) << 1) | (r >> 3);
    return (((kk * 4 + mt) * 32 + lane) * 4 + w) * 2 + (k & 1);
}

// ---------------------------------------------------------------------------
__global__ void zero_init_kernel(const int* __restrict__ sen_len) {
    int i = blockIdx.x * blockDim.x + threadIdx.x;
    if (i < (NBATCH * HID)) {          // both parities (as u32): 2*32768 halfs
        ((unsigned*)g_h0buf)[i] = 0u;
        ((unsigned*)g_h1buf)[i] = 0u;
    }
    if (i < 2 * 64) ((unsigned*)g_ctrs)[i] = 0u;
    if (i < 2) {
        int m = 1;
        for (int b = 0; b < 32; b++) m = max(m, sen_len[i * 32 + b]);
        g_maxsl2[i] = m;
    }
}

// ---------------------------------------------------------------------------
// tf32 tensor-core GEMM: g_E0h[M][2048] = A[M][512] @ W[2048][512]^T + (b1+b2)
// ---------------------------------------------------------------------------
#define GSTR 36
#define GBUF (128 * GSTR)

__global__ __launch_bounds__(256, 2) void gemm_e0_kernel(
    const float* __restrict__ A,
    const float* __restrict__ W,
    const float* __restrict__ bi1,
    const float* __restrict__ bi2,
    int M)
{
    extern __shared__ unsigned gsm[];
    unsigned* As = gsm;
    unsigned* Bs = gsm + 2 * GBUF;

    const int tid = threadIdx.x;
    const int lane = tid & 31;
    const int warp = tid >> 5;
    const int g = lane >> 2;
    const int tig = lane & 3;
    const int wm = warp & 1;
    const int wn = warp >> 1;
    const int m0 = blockIdx.y * 128;
    const int n0 = blockIdx.x * 128;

    float acc[4][4][4];
#pragma unroll
    for (int i = 0; i < 4; i++)
#pragma unroll
        for (int j = 0; j < 4; j++)
#pragma unroll
            for (int e = 0; e < 4; e++) acc[i][j][e] = 0.0f;

    int lrow[4], lc[4];
#pragma unroll
    for (int p = 0; p < 4; p++) {
        int id = tid + p * 256;
        lrow[p] = id >> 3;
        lc[p] = (id & 7) * 4;
    }

    {
#pragma unroll
        for (int p = 0; p < 4; p++) {
            int r = lrow[p], kc = lc[p];
            float4 va = make_float4(0.f, 0.f, 0.f, 0.f);
            if (m0 + r < M) va = *(const float4*)(A + (size_t)(m0 + r) * 512 + kc);
            *(uint4*)(As + r * GSTR + kc) = *(const uint4*)&va;
            float4 vb = *(const float4*)(W + (size_t)(n0 + r) * 512 + kc);
            *(uint4*)(Bs + r * GSTR + kc) = *(const uint4*)&vb;
        }
    }
    __syncthreads();

    float4 pa[4], pb[4];
    for (int it = 0; it < 16; it++) {
        int buf = it & 1;
        if (it < 15) {
            int k0 = (it + 1) * 32;
#pragma unroll
            for (int p = 0; p < 4; p++) {
                int r = lrow[p], kc = lc[p];
                pa[p] = make_float4(0.f, 0.f, 0.f, 0.f);
                if (m0 + r < M) pa[p] = *(const float4*)(A + (size_t)(m0 + r) * 512 + k0 + kc);
                pb[p] = *(const float4*)(W + (size_t)(n0 + r) * 512 + k0 + kc);
            }
        }
        const unsigned* Ab = As + buf * GBUF;
        const unsigned* Bb = Bs + buf * GBUF;
#pragma unroll
        for (int kk = 0; kk < 4; kk++) {
            int kb = kk * 8;
            unsigned af[4][4];
#pragma unroll
            for (int mf = 0; mf < 4; mf++) {
                int r = wm * 64 + mf * 16 + g;
                af[mf][0] = Ab[r * GSTR + kb + tig];
                af[mf][1] = Ab[(r + 8) * GSTR + kb + tig];
                af[mf][2] = Ab[r * GSTR + kb + tig + 4];
                af[mf][3] = Ab[(r + 8) * GSTR + kb + tig + 4];
            }
            unsigned bf[4][2];
#pragma unroll
            for (int nf = 0; nf < 4; nf++) {
                int n = wn * 32 + nf * 8 + g;
                bf[nf][0] = Bb[n * GSTR + kb + tig];
                bf[nf][1] = Bb[n * GSTR + kb + tig + 4];
            }
#pragma unroll
            for (int mf = 0; mf < 4; mf++)
#pragma unroll
                for (int nf = 0; nf < 4; nf++)
                    mma_tf32(acc[mf][nf], af[mf], bf[nf]);
        }
        if (it < 15) {
            unsigned* Ad = As + (buf ^ 1) * GBUF;
            unsigned* Bd = Bs + (buf ^ 1) * GBUF;
#pragma unroll
            for (int p = 0; p < 4; p++) {
                int r = lrow[p], kc = lc[p];
                *(uint4*)(Ad + r * GSTR + kc) = *(const uint4*)&pa[p];
                *(uint4*)(Bd + r * GSTR + kc) = *(const uint4*)&pb[p];
            }
        }
        __syncthreads();
    }

#pragma unroll
    for (int nf = 0; nf < 4; nf++) {
        int n = n0 + wn * 32 + nf * 8 + 2 * tig;
        float bb0 = bi1[n] + bi2[n];
        float bb1 = bi1[n + 1] + bi2[n + 1];
#pragma unroll
        for (int mf = 0; mf < 4; mf++) {
            int r = m0 + wm * 64 + mf * 16 + g;
            if (r < M) {
                __half2 v = __floats2half2_rn(acc[mf][nf][0] + bb0, acc[mf][nf][1] + bb1);
                *(__half2*)(g_E0h + (size_t)r * G4 + n) = v;
            }
            if (r + 8 < M) {
                __half2 v = __floats2half2_rn(acc[mf][nf][2] + bb0, acc[mf][nf][3] + bb1);
                *(__half2*)(g_E0h + (size_t)(r + 8) * G4 + n) = v;
            }
        }
    }
}

// ---------------------------------------------------------------------------
// Fused two-layer pipelined LSTM scan — ZERO-STAGING version.
// 128 CTAs x 256 threads. Block (ub = bid>>1, bh = bid&1) owns units
// [8ub,8ub+8) (32 gate rows) x batches [32bh,32bh+32). Two independent
// batch-half groups (own counter, own bound).
// Warp w = ks (0..7) owns k-slice [64ks, 64ks+64) and ALL 32 rows:
//   A fragments are PRIVATE to the warp -> loaded directly from
//   g_h0buf/g_h1buf via LDG.128.cg (no smem staging, no cp.async, no
//   pairwise barrier, no LDS). 16 LDG/thread, MLP-overlapped.
//   B frags (Whh0, Wih1, Whh1): [4 kk][4 nt][2] x3 = 96 regs, loaded once.
// 8-way k-partials reduced via smem red into the cell phase.
// Grid barrier: per-half counter + E0 prefetch in the poll window.
// ---------------------------------------------------------------------------
__global__ __launch_bounds__(SCAN_THREADS) void lstm_fused_kernel(
    const int* __restrict__ src,
    const float* __restrict__ Whh0,
    const float* __restrict__ Wih1,
    const float* __restrict__ Whh1,
    const float* __restrict__ bih1,
    const float* __restrict__ bhh1,
    const int* __restrict__ sen_len,
    float* __restrict__ final_out)
{
    extern __shared__ unsigned ssm[];
    float* red0 = (float*)ssm;                 // [8][32][NPAD]
    float* red1 = red0 + 8 * 32 * NPAD;        // [8][32][NPAD]

    const int tid = threadIdx.x;
    const int lane = tid & 31;
    const int ks = tid >> 5;         // warp = k-slice [64ks, 64ks+64)
    const int g = lane >> 2;
    const int tig = lane & 3;
    const int ub = blockIdx.x >> 1;
    const int bh = blockIdx.x & 1;
    const int u0 = ub * 8;

    // ---- B fragments in registers (once): Whh0, Wih1, Whh1 ----
    unsigned breg0[4][4][2], bregI[4][4][2], bregU[4][4][2];
#pragma unroll
    for (int kk = 0; kk < 4; kk++) {
#pragma unroll
        for (int nt = 0; nt < 4; nt++) {
            int n = nt * 8 + g;
            size_t row = (size_t)((n & 3) * 512 + u0 + (n >> 2)) * 512
                       + ks * 64 + kk * 16;
            {
                const float* wr = Whh0 + row;
                __half2 h0 = __floats2half2_rn(wr[2 * tig], wr[2 * tig + 1]);
                __half2 h1 = __floats2half2_rn(wr[2 * tig + 8], wr[2 * tig + 9]);
                breg0[kk][nt][0] = *(unsigned*)&h0;
                breg0[kk][nt][1] = *(unsigned*)&h1;
            }
            {
                const float* wr = Wih1 + row;
                __half2 h0 = __floats2half2_rn(wr[2 * tig], wr[2 * tig + 1]);
                __half2 h1 = __floats2half2_rn(wr[2 * tig + 8], wr[2 * tig + 9]);
                bregI[kk][nt][0] = *(unsigned*)&h0;
                bregI[kk][nt][1] = *(unsigned*)&h1;
            }
            {
                const float* wr = Whh1 + row;
                __half2 h0 = __floats2half2_rn(wr[2 * tig], wr[2 * tig + 1]);
                __half2 h1 = __floats2half2_rn(wr[2 * tig + 8], wr[2 * tig + 9]);
                bregU[kk][nt][0] = *(unsigned*)&h0;
                bregU[kk][nt][1] = *(unsigned*)&h1;
            }
        }
    }

    // ---- cell-phase mapping: thread = (unit u_loc, batch b_loc) ----
    const int u_loc = tid >> 5;          // 0..7
    const int b_loc = lane;              // 0..31
    const int b_glob = bh * 32 + b_loc;
    const int u_glob = u0 + u_loc;

    float bsum[4];
#pragma unroll
    for (int gt = 0; gt < 4; gt++)
        bsum[gt] = bih1[gt * 512 + u_glob] + bhh1[gt * 512 + u_glob];

    float c_l0 = 0.f, c_l1 = 0.f;
    const int sl = sen_len[b_glob];
    const int maxsl = g_maxsl2[bh];
    const int hi = hidx16(b_glob, u_glob);
    unsigned* ctr = &g_ctrs[bh][0];

    // ---- initial E0 prefetch (t = 0) ----
    float p[4];
    {
        int r = src[b_glob];
        const __half* e = g_E0h + (size_t)r * G4 + u_glob;
#pragma unroll
        for (int gt = 0; gt < 4; gt++) p[gt] = __half2float(e[gt * 512]);
    }

    for (int t = 0; t <= maxsl; t++) {
        const bool do_l0 = (t < maxsl);
        const bool do_l1 = (t >= 1);

        // ---- mma: A fragments straight from global (L2), private per warp ----
        {
            const uint4* h0p = (const uint4*)(g_h0buf[(t + 1) & 1]);
            const uint4* h1p = (const uint4*)(g_h1buf[t & 1]);

            float acc0[2][4][4], acc1[2][4][4];
#pragma unroll
            for (int mt2 = 0; mt2 < 2; mt2++)
#pragma unroll
                for (int nt = 0; nt < 4; nt++)
#pragma unroll
                    for (int e = 0; e < 4; e++) { acc0[mt2][nt][e] = 0.f; acc1[mt2][nt][e] = 0.f; }

#pragma unroll
            for (int kk = 0; kk < 4; kk++) {
                int kkg = ks * 4 + kk;
#pragma unroll
                for (int mt2 = 0; mt2 < 2; mt2++) {
                    int fidx = (kkg * 4 + 2 * bh + mt2) * 32 + lane;
                    uint4 a0 = ldcg4(h0p + fidx);
                    uint4 a1 = ldcg4(h1p + fidx);
#pragma unroll
                    for (int nt = 0; nt < 4; nt++) {
                        mma_f16(acc0[mt2][nt], (const unsigned*)&a0, breg0[kk][nt]);
                        mma_f16(acc1[mt2][nt], (const unsigned*)&a0, bregI[kk][nt]);
                        mma_f16(acc1[mt2][nt], (const unsigned*)&a1, bregU[kk][nt]);
                    }
                }
            }

            // ---- store k-partials: red[ks][m_loc][n] ----
#pragma unroll
            for (int mt2 = 0; mt2 < 2; mt2++)
#pragma unroll
                for (int nt = 0; nt < 4; nt++) {
                    int m_loc = mt2 * 16 + g;
                    int col = nt * 8 + 2 * tig;
                    float* rp0 = &red0[(ks * 32 + m_loc) * NPAD + col];
                    *(float2*)rp0 = make_float2(acc0[mt2][nt][0], acc0[mt2][nt][1]);
                    *(float2*)(rp0 + 8 * NPAD) = make_float2(acc0[mt2][nt][2], acc0[mt2][nt][3]);
                    float* rp1 = &red1[(ks * 32 + m_loc) * NPAD + col];
                    *(float2*)rp1 = make_float2(acc1[mt2][nt][0], acc1[mt2][nt][1]);
                    *(float2*)(rp1 + 8 * NPAD) = make_float2(acc1[mt2][nt][2], acc1[mt2][nt][3]);
                }
        }
        __syncthreads();

        // ---- layer0 cell: h_l0[t] ----
        if (do_l0) {
            float z[4];
#pragma unroll
            for (int gt = 0; gt < 4; gt++) z[gt] = p[gt];
#pragma unroll
            for (int w = 0; w < 8; w++) {
                float4 v = *(const float4*)&red0[(w * 32 + b_loc) * NPAD + u_loc * 4];
                z[0] += v.x; z[1] += v.y; z[2] += v.z; z[3] += v.w;
            }
            float ig = sig_(z[0]), fg = sig_(z[1]), gg = tanh_ap(z[2]), og = sig_(z[3]);
            c_l0 = fg * c_l0 + ig * gg;
            float hn = og * tanh_ap(c_l0);
            g_h0buf[t & 1][hi] = __float2half_rn(hn);
        }

        // ---- layer1 cell: h_l1[t-1] ----
        if (do_l1) {
            float z[4];
#pragma unroll
            for (int gt = 0; gt < 4; gt++) z[gt] = bsum[gt];
#pragma unroll
            for (int w = 0; w < 8; w++) {
                float4 v = *(const float4*)&red1[(w * 32 + b_loc) * NPAD + u_loc * 4];
                z[0] += v.x; z[1] += v.y; z[2] += v.z; z[3] += v.w;
            }
            float ig = sig_(z[0]), fg = sig_(z[1]), gg = tanh_ap(z[2]), og = sig_(z[3]);
            c_l1 = fg * c_l1 + ig * gg;
            float hn = og * tanh_ap(c_l1);
            g_h1buf[(t - 1) & 1][hi] = __float2half_rn(hn);
            if (t == sl) final_out[b_glob * HID + u_glob] = hn;
        }

        // ---- grid barrier (per-half counter) + E0 prefetch overlap ----
        __syncthreads();   // all h stores issued block-wide
        if (tid == 0) {
            asm volatile("red.release.gpu.global.add.u32 [%0], 1;"
                         :: "l"(ctr) : "memory");
        }
        // prefetch E0 for step t+1 while tid0 polls (independent of h)
        {
            int tt = (t + 1 < maxsl) ? (t + 1) : 0;
            int r = src[tt * NBATCH + b_glob];
            const __half* e = g_E0h + (size_t)r * G4 + u_glob;
#pragma unroll
            for (int gt = 0; gt < 4; gt++) p[gt] = __half2float(e[gt * 512]);
        }
        if (tid == 0) {
            unsigned tgt = 64u * (unsigned)(t + 1);
            while (ld_acq(ctr) < tgt) { }
        }
        __syncthreads();
    }
}

// ---------------------------------------------------------------------------
extern "C" void kernel_launch(void* const* d_in, const int* in_sizes, int n_in,
                              void* d_out, int out_size)
{
    const int*   src       = (const int*)  d_in[0];
    const int*   sen_len   = (const int*)  d_in[1];
    const float* emb_table = (const float*)d_in[2];
    const float* Wih0      = (const float*)d_in[3];
    const float* Whh0      = (const float*)d_in[4];
    const float* bih0      = (const float*)d_in[5];
    const float* bhh0      = (const float*)d_in[6];
    const float* Wih1      = (const float*)d_in[7];
    const float* Whh1      = (const float*)d_in[8];
    const float* bih1      = (const float*)d_in[9];
    const float* bhh1      = (const float*)d_in[10];
    float* out = (float*)d_out;

    const size_t gemm_smem = (size_t)4 * GBUF * sizeof(unsigned);        // 73728 B
    const size_t scan_smem = (size_t)(2 * 8 * 32 * NPAD) * sizeof(float); // 73728 B
    cudaFuncSetAttribute(gemm_e0_kernel,
                         cudaFuncAttributeMaxDynamicSharedMemorySize, (int)gemm_smem);
    cudaFuncSetAttribute(lstm_fused_kernel,
                         cudaFuncAttributeMaxDynamicSharedMemorySize, (int)scan_smem);

    // Phase 0: E0 = emb_table @ Wih0^T + (bih0+bhh0)   (10000 x 2048, fp16)
    {
        dim3 grid(G4 / 128, (NVOCAB + 127) / 128);
        gemm_e0_kernel<<<grid, 256, gemm_smem>>>(emb_table, Wih0, bih0, bhh0, NVOCAB);
    }

    // Phase 1: fused two-layer pipelined scan, decoupled batch halves
    zero_init_kernel<<<128, 512>>>(sen_len);
    lstm_fused_kernel<<<SCAN_BLOCKS, SCAN_THREADS, scan_smem>>>(
        src, Whh0, Wih1, Whh1, bih1, bhh1, sen_len, out);
}